// round 8
// baseline (speedup 1.0000x reference)
#include <cuda_runtime.h>
#include <cuda_bf16.h>
#include <cstdint>

#define M_DIM 8192
#define N_DIM 4096
#define K_DIM 4096

// ---------------- scratch (no allocations allowed) ----------------
__device__ float g_absmax[2];                  // [0]=x, [1]=W
__device__ int8_t g_qx[(size_t)M_DIM * K_DIM]; // 32 MB
__device__ int8_t g_qw[(size_t)N_DIM * K_DIM]; // 16 MB

// ---------------- init ----------------
__global__ void init_kernel() {
    if (threadIdx.x < 2) g_absmax[threadIdx.x] = 0.0f;
}

// ---------------- absmax reduction ----------------
__global__ void absmax_kernel(const float4* __restrict__ p, int n4, int slot) {
    float m = 0.0f;
    int stride = gridDim.x * blockDim.x;
    for (int i = blockIdx.x * blockDim.x + threadIdx.x; i < n4; i += stride) {
        float4 v = p[i];
        m = fmaxf(m, fmaxf(fmaxf(fabsf(v.x), fabsf(v.y)),
                           fmaxf(fabsf(v.z), fabsf(v.w))));
    }
    #pragma unroll
    for (int o = 16; o; o >>= 1) m = fmaxf(m, __shfl_xor_sync(0xFFFFFFFFu, m, o));
    __shared__ float sm[32];
    if ((threadIdx.x & 31) == 0) sm[threadIdx.x >> 5] = m;
    __syncthreads();
    if (threadIdx.x < 32) {
        m = (threadIdx.x < (blockDim.x >> 5)) ? sm[threadIdx.x] : 0.0f;
        #pragma unroll
        for (int o = 16; o; o >>= 1) m = fmaxf(m, __shfl_xor_sync(0xFFFFFFFFu, m, o));
        if (threadIdx.x == 0)
            atomicMax((unsigned int*)&g_absmax[slot], __float_as_uint(m));
    }
}

// ---------------- quantize to int8 (16 elems -> 16 bytes per thread) ----------------
__device__ __forceinline__ uint32_t pack4(float a, float b, float c, float d,
                                          float s, float lo) {
    int q0 = (int)fminf(fmaxf(rintf(a / s), lo), 127.0f);
    int q1 = (int)fminf(fmaxf(rintf(b / s), lo), 127.0f);
    int q2 = (int)fminf(fmaxf(rintf(c / s), lo), 127.0f);
    int q3 = (int)fminf(fmaxf(rintf(d / s), lo), 127.0f);
    return (uint32_t)(q0 & 0xFF) | ((uint32_t)(q1 & 0xFF) << 8) |
           ((uint32_t)(q2 & 0xFF) << 16) | ((uint32_t)(q3 & 0xFF) << 24);
}

// NOTE: output pointers are the __device__ globals, bound IN DEVICE CODE.
// (Passing &g_qx from host code passes the host shadow address — round-7 bug.)
__global__ void quant_x_kernel(const float4* __restrict__ in, int n16) {
    int i = blockIdx.x * blockDim.x + threadIdx.x;
    if (i >= n16) return;
    const float s = g_absmax[0] / 127.0f;
    float4 v0 = in[i * 4 + 0];
    float4 v1 = in[i * 4 + 1];
    float4 v2 = in[i * 4 + 2];
    float4 v3 = in[i * 4 + 3];
    uint4 o;
    o.x = pack4(v0.x, v0.y, v0.z, v0.w, s, -128.0f);
    o.y = pack4(v1.x, v1.y, v1.z, v1.w, s, -128.0f);
    o.z = pack4(v2.x, v2.y, v2.z, v2.w, s, -128.0f);
    o.w = pack4(v3.x, v3.y, v3.z, v3.w, s, -128.0f);
    ((uint4*)g_qx)[i] = o;
}

__global__ void quant_w_kernel(const float4* __restrict__ in, int n16) {
    int i = blockIdx.x * blockDim.x + threadIdx.x;
    if (i >= n16) return;
    const float s = g_absmax[1] / 127.0f;
    float4 v0 = in[i * 4 + 0];
    float4 v1 = in[i * 4 + 1];
    float4 v2 = in[i * 4 + 2];
    float4 v3 = in[i * 4 + 3];
    uint4 o;
    o.x = pack4(v0.x, v0.y, v0.z, v0.w, s, -127.0f);
    o.y = pack4(v1.x, v1.y, v1.z, v1.w, s, -127.0f);
    o.z = pack4(v2.x, v2.y, v2.z, v2.w, s, -127.0f);
    o.w = pack4(v3.x, v3.y, v3.z, v3.w, s, -127.0f);
    ((uint4*)g_qw)[i] = o;
}

// ---------------- GEMM: C[M,N] = qx[M,K] * qw[N,K]^T (int8, s32 accum) ----------------
#define BM 128
#define BN 128
#define BK 64    // 64 int8 = 64 bytes per k-slice row
#define LDT 80   // padded smem row stride in BYTES

__device__ __forceinline__ unsigned smem_u32(const void* p) {
    return (unsigned)__cvta_generic_to_shared(p);
}

__device__ __forceinline__ void ldsm4(unsigned r[4], unsigned addr) {
    asm volatile("ldmatrix.sync.aligned.m8n8.x4.shared.b16 {%0,%1,%2,%3}, [%4];"
                 : "=r"(r[0]), "=r"(r[1]), "=r"(r[2]), "=r"(r[3])
                 : "r"(addr));
}

__device__ __forceinline__ void mma_s8(int c[4],
                                       unsigned a0, unsigned a1, unsigned a2, unsigned a3,
                                       unsigned b0, unsigned b1) {
    asm volatile(
        "mma.sync.aligned.m16n8k32.row.col.s32.s8.s8.s32 "
        "{%0,%1,%2,%3}, {%4,%5,%6,%7}, {%8,%9}, {%0,%1,%2,%3};"
        : "+r"(c[0]), "+r"(c[1]), "+r"(c[2]), "+r"(c[3])
        : "r"(a0), "r"(a1), "r"(a2), "r"(a3), "r"(b0), "r"(b1));
}

__global__ __launch_bounds__(256, 1) void gemm_kernel(float* __restrict__ C,
                                                      const float* __restrict__ bias) {
    __shared__ int8_t sA[2][BM * LDT];
    __shared__ int8_t sB[2][BN * LDT];

    const int tid  = threadIdx.x;
    const int lane = tid & 31;
    const int warp = tid >> 5;
    const int wm   = warp >> 2;   // 0..1  (64 rows each)
    const int wn   = warp & 3;    // 0..3  (32 cols each)
    const int bm0  = blockIdx.y * BM;
    const int bn0  = blockIdx.x * BN;

    const int8_t* gA = g_qx + (size_t)bm0 * K_DIM;
    const int8_t* gB = g_qw + (size_t)bn0 * K_DIM;

    int acc[4][4][4];
    #pragma unroll
    for (int mi = 0; mi < 4; ++mi)
        #pragma unroll
        for (int ni = 0; ni < 4; ++ni)
            #pragma unroll
            for (int r = 0; r < 4; ++r) acc[mi][ni][r] = 0;

    // 16B-chunk load mapping: 128 rows x 4 chunks/row (64B rows)
    const int lrow = tid >> 2;          // 0..63
    const int lcol = (tid & 3) * 16;    // byte offset within 64B k-slice

    auto load_tile = [&](int kt, int buf) {
        const int k0 = kt * BK;
        {
            const int8_t* src = gA + (size_t)lrow * K_DIM + k0 + lcol;
            unsigned dst = smem_u32(&sA[buf][lrow * LDT + lcol]);
            asm volatile("cp.async.cg.shared.global [%0], [%1], 16;\n" :: "r"(dst), "l"(src));
            src += (size_t)64 * K_DIM;
            dst = smem_u32(&sA[buf][(lrow + 64) * LDT + lcol]);
            asm volatile("cp.async.cg.shared.global [%0], [%1], 16;\n" :: "r"(dst), "l"(src));
        }
        {
            const int8_t* src = gB + (size_t)lrow * K_DIM + k0 + lcol;
            unsigned dst = smem_u32(&sB[buf][lrow * LDT + lcol]);
            asm volatile("cp.async.cg.shared.global [%0], [%1], 16;\n" :: "r"(dst), "l"(src));
            src += (size_t)64 * K_DIM;
            dst = smem_u32(&sB[buf][(lrow + 64) * LDT + lcol]);
            asm volatile("cp.async.cg.shared.global [%0], [%1], 16;\n" :: "r"(dst), "l"(src));
        }
    };

    constexpr int KT = K_DIM / BK;  // 64

    load_tile(0, 0);
    asm volatile("cp.async.commit_group;\n");

    for (int kt = 0; kt < KT; ++kt) {
        if (kt + 1 < KT) {
            load_tile(kt + 1, (kt + 1) & 1);
            asm volatile("cp.async.commit_group;\n");
            asm volatile("cp.async.wait_group 1;\n");
        } else {
            asm volatile("cp.async.wait_group 0;\n");
        }
        __syncthreads();

        const int buf = kt & 1;
        #pragma unroll
        for (int ks = 0; ks < 2; ++ks) {   // two k32 steps per 64B tile
            unsigned a[4][4], bb[2][4];
            #pragma unroll
            for (int mi = 0; mi < 4; ++mi) {
                const int8_t* p =
                    &sA[buf][(wm * 64 + mi * 16 + (lane & 15)) * LDT +
                             ks * 32 + (lane >> 4) * 16];
                ldsm4(a[mi], smem_u32(p));
            }
            #pragma unroll
            for (int nj = 0; nj < 2; ++nj) {
                const int8_t* p =
                    &sB[buf][(wn * 32 + nj * 16 + (lane & 7) + ((lane >> 4) << 3)) * LDT +
                             ks * 32 + ((lane >> 3) & 1) * 16];
                ldsm4(bb[nj], smem_u32(p));
            }
            #pragma unroll
            for (int mi = 0; mi < 4; ++mi)
                #pragma unroll
                for (int ni = 0; ni < 4; ++ni)
                    mma_s8(acc[mi][ni], a[mi][0], a[mi][1], a[mi][2], a[mi][3],
                           bb[ni >> 1][(ni & 1) * 2], bb[ni >> 1][(ni & 1) * 2 + 1]);
        }
        __syncthreads();
    }

    // epilogue: out = (4*s_x*s_w)*acc + 4*b   (acc is exact int32)
    const float alpha = 4.0f * (g_absmax[0] / 127.0f) * (g_absmax[1] / 127.0f);

    #pragma unroll
    for (int mi = 0; mi < 4; ++mi) {
        const int r0 = bm0 + wm * 64 + mi * 16 + (lane >> 2);
        #pragma unroll
        for (int ni = 0; ni < 4; ++ni) {
            const int c0 = bn0 + wn * 32 + ni * 8 + (lane & 3) * 2;
            const float b0v = 4.0f * bias[c0];
            const float b1v = 4.0f * bias[c0 + 1];
            float* o0 = C + (size_t)r0 * N_DIM + c0;
            o0[0] = alpha * (float)acc[mi][ni][0] + b0v;
            o0[1] = alpha * (float)acc[mi][ni][1] + b1v;
            float* o1 = C + (size_t)(r0 + 8) * N_DIM + c0;
            o1[0] = alpha * (float)acc[mi][ni][2] + b0v;
            o1[1] = alpha * (float)acc[mi][ni][3] + b1v;
        }
    }
}

// ---------------- launch ----------------
extern "C" void kernel_launch(void* const* d_in, const int* in_sizes, int n_in,
                              void* d_out, int out_size) {
    const float* x = (const float*)d_in[0];
    const float* W = (const float*)d_in[1];
    const float* b = (const float*)d_in[2];
    float* out = (float*)d_out;

    const int n4x  = (M_DIM * K_DIM) / 4;
    const int n4w  = (N_DIM * K_DIM) / 4;
    const int n16x = (M_DIM * K_DIM) / 16;
    const int n16w = (N_DIM * K_DIM) / 16;

    init_kernel<<<1, 32>>>();
    absmax_kernel<<<2048, 256>>>((const float4*)x, n4x, 0);
    absmax_kernel<<<2048, 256>>>((const float4*)W, n4w, 1);
    quant_x_kernel<<<(n16x + 255) / 256, 256>>>((const float4*)x, n16x);
    quant_w_kernel<<<(n16w + 255) / 256, 256>>>((const float4*)W, n16w);

    dim3 grid(N_DIM / BN, M_DIM / BM);  // (32, 64): x-fast over N for L2 reuse
    gemm_kernel<<<grid, 256>>>(out, b);
}

// round 9
// speedup vs baseline: 1.7334x; 1.7334x over previous
#include <cuda_runtime.h>
#include <cuda_bf16.h>
#include <cstdint>

#define M_DIM 8192
#define N_DIM 4096
#define K_DIM 4096

// ---------------- scratch (no allocations allowed) ----------------
__device__ float g_absmax[2];                         // [0]=x, [1]=W
__device__ __nv_bfloat16 g_qx[(size_t)M_DIM * K_DIM]; // 64 MB
__device__ __nv_bfloat16 g_qw[(size_t)N_DIM * K_DIM]; // 32 MB

// ---------------- init ----------------
__global__ void init_kernel() {
    if (threadIdx.x < 2) g_absmax[threadIdx.x] = 0.0f;
}

// ---------------- absmax reduction ----------------
__global__ void absmax_kernel(const float4* __restrict__ p, int n4, int slot) {
    float m = 0.0f;
    int stride = gridDim.x * blockDim.x;
    for (int i = blockIdx.x * blockDim.x + threadIdx.x; i < n4; i += stride) {
        float4 v = p[i];
        m = fmaxf(m, fmaxf(fmaxf(fabsf(v.x), fabsf(v.y)),
                           fmaxf(fabsf(v.z), fabsf(v.w))));
    }
    #pragma unroll
    for (int o = 16; o; o >>= 1) m = fmaxf(m, __shfl_xor_sync(0xFFFFFFFFu, m, o));
    __shared__ float sm[32];
    if ((threadIdx.x & 31) == 0) sm[threadIdx.x >> 5] = m;
    __syncthreads();
    if (threadIdx.x < 32) {
        m = (threadIdx.x < (blockDim.x >> 5)) ? sm[threadIdx.x] : 0.0f;
        #pragma unroll
        for (int o = 16; o; o >>= 1) m = fmaxf(m, __shfl_xor_sync(0xFFFFFFFFu, m, o));
        if (threadIdx.x == 0)
            atomicMax((unsigned int*)&g_absmax[slot], __float_as_uint(m));
    }
}

// ---------------- quantize to integer-valued bf16 (8 elems/thread) ----------------
__device__ __forceinline__ uint32_t qpack2(float a, float b, float s, float lo) {
    float q0 = fminf(fmaxf(rintf(a / s), lo), 127.0f);
    float q1 = fminf(fmaxf(rintf(b / s), lo), 127.0f);
    __nv_bfloat162 h = __floats2bfloat162_rn(q0, q1);
    return *(uint32_t*)&h;
}

__global__ void quant_x_kernel(const float4* __restrict__ in, int n8) {
    int i = blockIdx.x * blockDim.x + threadIdx.x;
    if (i >= n8) return;
    const float s = g_absmax[0] / 127.0f;
    float4 v0 = in[i * 2 + 0];
    float4 v1 = in[i * 2 + 1];
    uint4 o;
    o.x = qpack2(v0.x, v0.y, s, -128.0f);
    o.y = qpack2(v0.z, v0.w, s, -128.0f);
    o.z = qpack2(v1.x, v1.y, s, -128.0f);
    o.w = qpack2(v1.z, v1.w, s, -128.0f);
    ((uint4*)g_qx)[i] = o;   // device-side symbol binding (round-7 lesson)
}

__global__ void quant_w_kernel(const float4* __restrict__ in, int n8) {
    int i = blockIdx.x * blockDim.x + threadIdx.x;
    if (i >= n8) return;
    const float s = g_absmax[1] / 127.0f;
    float4 v0 = in[i * 2 + 0];
    float4 v1 = in[i * 2 + 1];
    uint4 o;
    o.x = qpack2(v0.x, v0.y, s, -127.0f);
    o.y = qpack2(v0.z, v0.w, s, -127.0f);
    o.z = qpack2(v1.x, v1.y, s, -127.0f);
    o.w = qpack2(v1.z, v1.w, s, -127.0f);
    ((uint4*)g_qw)[i] = o;
}

// ---------------- GEMM: C[M,N] = qx[M,K] * qw[N,K]^T ----------------
#define BM 128
#define BN 128
#define BK 64          // 64 bf16 = 128 bytes per row
#define NSTAGE 4
#define KT (K_DIM / BK)            // 64
#define A_BYTES (BM * 128)         // 16 KB
#define STAGE_BYTES (2 * A_BYTES)  // A + B = 32 KB
#define SMEM_DYN (NSTAGE * STAGE_BYTES + 128)

__device__ __forceinline__ unsigned smem_u32(const void* p) {
    return (unsigned)__cvta_generic_to_shared(p);
}

__device__ __forceinline__ void ldsm4(unsigned r[4], unsigned addr) {
    asm volatile("ldmatrix.sync.aligned.m8n8.x4.shared.b16 {%0,%1,%2,%3}, [%4];"
                 : "=r"(r[0]), "=r"(r[1]), "=r"(r[2]), "=r"(r[3])
                 : "r"(addr));
}

__device__ __forceinline__ void mma_bf16(float c[4],
                                         unsigned a0, unsigned a1, unsigned a2, unsigned a3,
                                         unsigned b0, unsigned b1) {
    asm volatile(
        "mma.sync.aligned.m16n8k16.row.col.f32.bf16.bf16.f32 "
        "{%0,%1,%2,%3}, {%4,%5,%6,%7}, {%8,%9}, {%0,%1,%2,%3};"
        : "+f"(c[0]), "+f"(c[1]), "+f"(c[2]), "+f"(c[3])
        : "r"(a0), "r"(a1), "r"(a2), "r"(a3), "r"(b0), "r"(b1));
}

__global__ __launch_bounds__(256, 1) void gemm_kernel(float* __restrict__ C,
                                                      const float* __restrict__ bias) {
    extern __shared__ __align__(128) uint8_t dynsmem[];
    uint32_t smbase = smem_u32(dynsmem);
    smbase = (smbase + 127u) & ~127u;

    const int tid  = threadIdx.x;
    const int lane = tid & 31;
    const int warp = tid >> 5;
    const int wm   = warp >> 2;   // 0..1  (64 rows)
    const int wn   = warp & 3;    // 0..3  (32 cols)
    const int bm0  = blockIdx.y * BM;
    const int bn0  = blockIdx.x * BN;

    const __nv_bfloat16* gA = g_qx + (size_t)bm0 * K_DIM;
    const __nv_bfloat16* gB = g_qw + (size_t)bn0 * K_DIM;

    float acc[4][4][4];
    #pragma unroll
    for (int mi = 0; mi < 4; ++mi)
        #pragma unroll
        for (int ni = 0; ni < 4; ++ni)
            #pragma unroll
            for (int r = 0; r < 4; ++r) acc[mi][ni][r] = 0.0f;

    // stage loader: 128 rows x 8 x 16B chunks each for A and B, XOR-swizzled
    const int lrow = tid >> 1;                 // 0..127
    const int lc0  = (tid & 1) * 4;            // chunks 0-3 or 4-7

    auto load_stage = [&](int kt, int stage) {
        const uint32_t sa = smbase + stage * STAGE_BYTES;
        const uint32_t sb = sa + A_BYTES;
        const int k0 = kt * BK;
        #pragma unroll
        for (int c = 0; c < 4; ++c) {
            const int ch = lc0 + c;
            const uint32_t off = lrow * 128 + ((ch ^ (lrow & 7)) << 4);
            const void* srcA = gA + (size_t)lrow * K_DIM + k0 + ch * 8;
            asm volatile("cp.async.cg.shared.global [%0], [%1], 16;\n"
                         :: "r"(sa + off), "l"(srcA));
            const void* srcB = gB + (size_t)lrow * K_DIM + k0 + ch * 8;
            asm volatile("cp.async.cg.shared.global [%0], [%1], 16;\n"
                         :: "r"(sb + off), "l"(srcB));
        }
        asm volatile("cp.async.commit_group;\n" ::: "memory");
    };

    load_stage(0, 0);
    load_stage(1, 1);
    load_stage(2, 2);

    // fragment address components (lane-invariant across ks)
    const int arow[4] = {wm * 64 + 0 * 16 + (lane & 15), wm * 64 + 1 * 16 + (lane & 15),
                         wm * 64 + 2 * 16 + (lane & 15), wm * 64 + 3 * 16 + (lane & 15)};
    const int abit = lane >> 4;                 // chunk low bit for A
    const int brow[2] = {wn * 32 + 0 * 16 + (lane & 7) + ((lane >> 4) << 3),
                         wn * 32 + 1 * 16 + (lane & 7) + ((lane >> 4) << 3)};
    const int bbit = (lane >> 3) & 1;           // chunk low bit for B

    unsigned af[2][4][4], bf[2][2][4];

    auto load_frags = [&](uint32_t sa, uint32_t sb, int ks, int buf) {
        #pragma unroll
        for (int mi = 0; mi < 4; ++mi) {
            const int ch = ks * 2 + abit;
            ldsm4(af[buf][mi], sa + arow[mi] * 128 + ((ch ^ (arow[mi] & 7)) << 4));
        }
        #pragma unroll
        for (int nj = 0; nj < 2; ++nj) {
            const int ch = ks * 2 + bbit;
            ldsm4(bf[buf][nj], sb + brow[nj] * 128 + ((ch ^ (brow[nj] & 7)) << 4));
        }
    };

    for (int kt = 0; kt < KT; ++kt) {
        asm volatile("cp.async.wait_group 2;\n" ::: "memory");
        __syncthreads();
        // prefetch stage kt+3 (overwrites buffer of kt-1; all warps passed the
        // barrier above, hence finished reading it)
        if (kt + 3 < KT) load_stage(kt + 3, (kt + 3) & 3);
        else asm volatile("cp.async.commit_group;\n" ::: "memory");  // keep counts aligned

        const uint32_t sa = smbase + (kt & 3) * STAGE_BYTES;
        const uint32_t sb = sa + A_BYTES;

        load_frags(sa, sb, 0, 0);
        #pragma unroll
        for (int ks = 0; ks < 4; ++ks) {        // BK/16
            const int cur = ks & 1;
            if (ks < 3) load_frags(sa, sb, ks + 1, cur ^ 1);
            #pragma unroll
            for (int mi = 0; mi < 4; ++mi)
                #pragma unroll
                for (int ni = 0; ni < 4; ++ni)
                    mma_bf16(acc[mi][ni],
                             af[cur][mi][0], af[cur][mi][1], af[cur][mi][2], af[cur][mi][3],
                             bf[cur][ni >> 1][(ni & 1) * 2], bf[cur][ni >> 1][(ni & 1) * 2 + 1]);
        }
    }

    // epilogue: out = (4*s_x*s_w)*acc + 4*b
    const float alpha = 4.0f * (g_absmax[0] / 127.0f) * (g_absmax[1] / 127.0f);

    #pragma unroll
    for (int mi = 0; mi < 4; ++mi) {
        const int r0 = bm0 + wm * 64 + mi * 16 + (lane >> 2);
        #pragma unroll
        for (int ni = 0; ni < 4; ++ni) {
            const int c0 = bn0 + wn * 32 + ni * 8 + (lane & 3) * 2;
            const float b0v = 4.0f * bias[c0];
            const float b1v = 4.0f * bias[c0 + 1];
            float* o0 = C + (size_t)r0 * N_DIM + c0;
            o0[0] = alpha * acc[mi][ni][0] + b0v;
            o0[1] = alpha * acc[mi][ni][1] + b1v;
            float* o1 = C + (size_t)(r0 + 8) * N_DIM + c0;
            o1[0] = alpha * acc[mi][ni][2] + b0v;
            o1[1] = alpha * acc[mi][ni][3] + b1v;
        }
    }
}

// ---------------- launch ----------------
extern "C" void kernel_launch(void* const* d_in, const int* in_sizes, int n_in,
                              void* d_out, int out_size) {
    const float* x = (const float*)d_in[0];
    const float* W = (const float*)d_in[1];
    const float* b = (const float*)d_in[2];
    float* out = (float*)d_out;

    const int n4x = (M_DIM * K_DIM) / 4;
    const int n4w = (N_DIM * K_DIM) / 4;
    const int n8x = (M_DIM * K_DIM) / 8;
    const int n8w = (N_DIM * K_DIM) / 8;

    init_kernel<<<1, 32>>>();
    absmax_kernel<<<2048, 256>>>((const float4*)x, n4x, 0);
    absmax_kernel<<<2048, 256>>>((const float4*)W, n4w, 1);
    quant_x_kernel<<<(n8x + 255) / 256, 256>>>((const float4*)x, n8x);
    quant_w_kernel<<<(n8w + 255) / 256, 256>>>((const float4*)W, n8w);

    static bool attr_set = false;
    if (!attr_set) {
        cudaFuncSetAttribute(gemm_kernel,
                             cudaFuncAttributeMaxDynamicSharedMemorySize, SMEM_DYN);
        attr_set = true;
    }
    dim3 grid(N_DIM / BN, M_DIM / BM);  // (32, 64): x-fast over N for L2 reuse
    gemm_kernel<<<grid, 256, SMEM_DYN>>>(out, b);
}

// round 10
// speedup vs baseline: 2.6087x; 1.5049x over previous
#include <cuda_runtime.h>
#include <cuda_bf16.h>
#include <cstdint>

#define M_DIM 8192
#define N_DIM 4096
#define K_DIM 4096

// ---------------- scratch (no allocations allowed) ----------------
__device__ float g_absmax[2];                         // [0]=x, [1]=W
__device__ __nv_bfloat16 g_qx[(size_t)M_DIM * K_DIM]; // 64 MB
__device__ __nv_bfloat16 g_qw[(size_t)N_DIM * K_DIM]; // 32 MB

// ---------------- init ----------------
__global__ void init_kernel() {
    if (threadIdx.x < 2) g_absmax[threadIdx.x] = 0.0f;
}

// ---------------- absmax reduction ----------------
__global__ void absmax_kernel(const float4* __restrict__ p, int n4, int slot) {
    float m = 0.0f;
    int stride = gridDim.x * blockDim.x;
    for (int i = blockIdx.x * blockDim.x + threadIdx.x; i < n4; i += stride) {
        float4 v = p[i];
        m = fmaxf(m, fmaxf(fmaxf(fabsf(v.x), fabsf(v.y)),
                           fmaxf(fabsf(v.z), fabsf(v.w))));
    }
    #pragma unroll
    for (int o = 16; o; o >>= 1) m = fmaxf(m, __shfl_xor_sync(0xFFFFFFFFu, m, o));
    __shared__ float sm[32];
    if ((threadIdx.x & 31) == 0) sm[threadIdx.x >> 5] = m;
    __syncthreads();
    if (threadIdx.x < 32) {
        m = (threadIdx.x < (blockDim.x >> 5)) ? sm[threadIdx.x] : 0.0f;
        #pragma unroll
        for (int o = 16; o; o >>= 1) m = fmaxf(m, __shfl_xor_sync(0xFFFFFFFFu, m, o));
        if (threadIdx.x == 0)
            atomicMax((unsigned int*)&g_absmax[slot], __float_as_uint(m));
    }
}

// ---------------- quantize to integer-valued bf16 (8 elems/thread) ----------------
__device__ __forceinline__ uint32_t qpack2(float a, float b, float s, float lo) {
    float q0 = fminf(fmaxf(rintf(a / s), lo), 127.0f);
    float q1 = fminf(fmaxf(rintf(b / s), lo), 127.0f);
    __nv_bfloat162 h = __floats2bfloat162_rn(q0, q1);
    return *(uint32_t*)&h;
}

__global__ void quant_x_kernel(const float4* __restrict__ in, int n8) {
    int i = blockIdx.x * blockDim.x + threadIdx.x;
    if (i >= n8) return;
    const float s = g_absmax[0] / 127.0f;
    float4 v0 = in[i * 2 + 0];
    float4 v1 = in[i * 2 + 1];
    uint4 o;
    o.x = qpack2(v0.x, v0.y, s, -128.0f);
    o.y = qpack2(v0.z, v0.w, s, -128.0f);
    o.z = qpack2(v1.x, v1.y, s, -128.0f);
    o.w = qpack2(v1.z, v1.w, s, -128.0f);
    ((uint4*)g_qx)[i] = o;   // device-side symbol binding (round-7 lesson)
}

__global__ void quant_w_kernel(const float4* __restrict__ in, int n8) {
    int i = blockIdx.x * blockDim.x + threadIdx.x;
    if (i >= n8) return;
    const float s = g_absmax[1] / 127.0f;
    float4 v0 = in[i * 2 + 0];
    float4 v1 = in[i * 2 + 1];
    uint4 o;
    o.x = qpack2(v0.x, v0.y, s, -127.0f);
    o.y = qpack2(v0.z, v0.w, s, -127.0f);
    o.z = qpack2(v1.x, v1.y, s, -127.0f);
    o.w = qpack2(v1.z, v1.w, s, -127.0f);
    ((uint4*)g_qw)[i] = o;
}

// ---------------- GEMM: C[M,N] = qx[M,K] * qw[N,K]^T ----------------
#define BM 128
#define BN 256
#define BK 64          // 64 bf16 = 128 bytes per row
#define NTHREADS 512   // 16 warps: 2 (M) x 8 (N); 4 warps per SMSP
#define NSTAGE 4
#define KT (K_DIM / BK)            // 64
#define A_BYTES (BM * 128)         // 16 KB
#define B_BYTES (BN * 128)         // 32 KB
#define STAGE_BYTES (A_BYTES + B_BYTES)  // 48 KB
#define SMEM_DYN (NSTAGE * STAGE_BYTES + 128)  // 192 KB + pad

__device__ __forceinline__ unsigned smem_u32(const void* p) {
    return (unsigned)__cvta_generic_to_shared(p);
}

__device__ __forceinline__ void ldsm4(unsigned r[4], unsigned addr) {
    asm volatile("ldmatrix.sync.aligned.m8n8.x4.shared.b16 {%0,%1,%2,%3}, [%4];"
                 : "=r"(r[0]), "=r"(r[1]), "=r"(r[2]), "=r"(r[3])
                 : "r"(addr));
}

__device__ __forceinline__ void mma_bf16(float c[4],
                                         unsigned a0, unsigned a1, unsigned a2, unsigned a3,
                                         unsigned b0, unsigned b1) {
    asm volatile(
        "mma.sync.aligned.m16n8k16.row.col.f32.bf16.bf16.f32 "
        "{%0,%1,%2,%3}, {%4,%5,%6,%7}, {%8,%9}, {%0,%1,%2,%3};"
        : "+f"(c[0]), "+f"(c[1]), "+f"(c[2]), "+f"(c[3])
        : "r"(a0), "r"(a1), "r"(a2), "r"(a3), "r"(b0), "r"(b1));
}

__global__ __launch_bounds__(NTHREADS, 1) void gemm_kernel(float* __restrict__ C,
                                                           const float* __restrict__ bias) {
    extern __shared__ __align__(128) uint8_t dynsmem[];
    uint32_t smbase = smem_u32(dynsmem);
    smbase = (smbase + 127u) & ~127u;

    const int tid  = threadIdx.x;
    const int lane = tid & 31;
    const int warp = tid >> 5;
    const int wm   = warp >> 3;   // 0..1  (64 rows)
    const int wn   = warp & 7;    // 0..7  (32 cols)
    const int bm0  = blockIdx.y * BM;
    const int bn0  = blockIdx.x * BN;

    const __nv_bfloat16* gA = g_qx + (size_t)bm0 * K_DIM;
    const __nv_bfloat16* gB = g_qw + (size_t)bn0 * K_DIM;

    float acc[4][4][4];
    #pragma unroll
    for (int mi = 0; mi < 4; ++mi)
        #pragma unroll
        for (int ni = 0; ni < 4; ++ni)
            #pragma unroll
            for (int r = 0; r < 4; ++r) acc[mi][ni][r] = 0.0f;

    // stage loader: A = 1024 chunks (2/thread), B = 2048 chunks (4/thread)
    auto load_stage = [&](int kt, int stage) {
        const uint32_t sa = smbase + stage * STAGE_BYTES;
        const uint32_t sb = sa + A_BYTES;
        const int k0 = kt * BK;
        #pragma unroll
        for (int i = 0; i < 2; ++i) {
            const int id  = tid + i * NTHREADS;
            const int row = id >> 3, ch = id & 7;
            const uint32_t off = row * 128 + ((ch ^ (row & 7)) << 4);
            const void* src = gA + (size_t)row * K_DIM + k0 + ch * 8;
            asm volatile("cp.async.cg.shared.global [%0], [%1], 16;\n"
                         :: "r"(sa + off), "l"(src));
        }
        #pragma unroll
        for (int i = 0; i < 4; ++i) {
            const int id  = tid + i * NTHREADS;
            const int row = id >> 3, ch = id & 7;
            const uint32_t off = row * 128 + ((ch ^ (row & 7)) << 4);
            const void* src = gB + (size_t)row * K_DIM + k0 + ch * 8;
            asm volatile("cp.async.cg.shared.global [%0], [%1], 16;\n"
                         :: "r"(sb + off), "l"(src));
        }
        asm volatile("cp.async.commit_group;\n" ::: "memory");
    };

    load_stage(0, 0);
    load_stage(1, 1);
    load_stage(2, 2);

    // fragment address components
    const int arow[4] = {wm * 64 + 0 * 16 + (lane & 15), wm * 64 + 1 * 16 + (lane & 15),
                         wm * 64 + 2 * 16 + (lane & 15), wm * 64 + 3 * 16 + (lane & 15)};
    const int abit = lane >> 4;
    const int brow[2] = {wn * 32 + 0 * 16 + (lane & 7) + ((lane >> 4) << 3),
                         wn * 32 + 1 * 16 + (lane & 7) + ((lane >> 4) << 3)};
    const int bbit = (lane >> 3) & 1;

    for (int kt = 0; kt < KT; ++kt) {
        asm volatile("cp.async.wait_group 2;\n" ::: "memory");
        __syncthreads();
        if (kt + 3 < KT) load_stage(kt + 3, (kt + 3) & 3);
        else asm volatile("cp.async.commit_group;\n" ::: "memory");

        const uint32_t sa = smbase + (kt & 3) * STAGE_BYTES;
        const uint32_t sb = sa + A_BYTES;

        #pragma unroll
        for (int ks = 0; ks < 4; ++ks) {        // BK/16; single-buffered frags —
            unsigned af[4][4], bf[2][4];        // bubbles covered by 4 warps/SMSP
            #pragma unroll
            for (int mi = 0; mi < 4; ++mi) {
                const int ch = ks * 2 + abit;
                ldsm4(af[mi], sa + arow[mi] * 128 + ((ch ^ (arow[mi] & 7)) << 4));
            }
            #pragma unroll
            for (int nj = 0; nj < 2; ++nj) {
                const int ch = ks * 2 + bbit;
                ldsm4(bf[nj], sb + brow[nj] * 128 + ((ch ^ (brow[nj] & 7)) << 4));
            }
            #pragma unroll
            for (int mi = 0; mi < 4; ++mi)
                #pragma unroll
                for (int ni = 0; ni < 4; ++ni)
                    mma_bf16(acc[mi][ni],
                             af[mi][0], af[mi][1], af[mi][2], af[mi][3],
                             bf[ni >> 1][(ni & 1) * 2], bf[ni >> 1][(ni & 1) * 2 + 1]);
        }
    }

    // epilogue: out = (4*s_x*s_w)*acc + 4*b
    const float alpha = 4.0f * (g_absmax[0] / 127.0f) * (g_absmax[1] / 127.0f);

    #pragma unroll
    for (int mi = 0; mi < 4; ++mi) {
        const int r0 = bm0 + wm * 64 + mi * 16 + (lane >> 2);
        #pragma unroll
        for (int ni = 0; ni < 4; ++ni) {
            const int c0 = bn0 + wn * 32 + ni * 8 + (lane & 3) * 2;
            const float b0v = 4.0f * bias[c0];
            const float b1v = 4.0f * bias[c0 + 1];
            float* o0 = C + (size_t)r0 * N_DIM + c0;
            o0[0] = alpha * acc[mi][ni][0] + b0v;
            o0[1] = alpha * acc[mi][ni][1] + b1v;
            float* o1 = C + (size_t)(r0 + 8) * N_DIM + c0;
            o1[0] = alpha * acc[mi][ni][2] + b0v;
            o1[1] = alpha * acc[mi][ni][3] + b1v;
        }
    }
}

// ---------------- launch ----------------
extern "C" void kernel_launch(void* const* d_in, const int* in_sizes, int n_in,
                              void* d_out, int out_size) {
    const float* x = (const float*)d_in[0];
    const float* W = (const float*)d_in[1];
    const float* b = (const float*)d_in[2];
    float* out = (float*)d_out;

    const int n4x = (M_DIM * K_DIM) / 4;
    const int n4w = (N_DIM * K_DIM) / 4;
    const int n8x = (M_DIM * K_DIM) / 8;
    const int n8w = (N_DIM * K_DIM) / 8;

    init_kernel<<<1, 32>>>();
    absmax_kernel<<<2048, 256>>>((const float4*)x, n4x, 0);
    absmax_kernel<<<2048, 256>>>((const float4*)W, n4w, 1);
    quant_x_kernel<<<(n8x + 255) / 256, 256>>>((const float4*)x, n8x);
    quant_w_kernel<<<(n8w + 255) / 256, 256>>>((const float4*)W, n8w);

    static bool attr_set = false;
    if (!attr_set) {
        cudaFuncSetAttribute(gemm_kernel,
                             cudaFuncAttributeMaxDynamicSharedMemorySize, SMEM_DYN);
        attr_set = true;
    }
    dim3 grid(N_DIM / BN, M_DIM / BM);  // (16, 64)
    gemm_kernel<<<grid, NTHREADS, SMEM_DYN>>>(out, b);
}